// round 8
// baseline (speedup 1.0000x reference)
#include <cuda_runtime.h>
#include <cuda_bf16.h>
#include <cstdint>

// ChannelBlockImportanceGate: forward value == hard top-k block mask.
// features [8,256,132,132] f32, enabled int32. BLOCK=8 -> 17x17=289 blocks,
// keep = 72. Ties: lower flat index wins (lax.top_k).
//
// R8: directional split. K1 = pure-read mask computation (R6 cp.async
// machinery, bitwise-identical pooled sums) writing a 2.4MB block-mask
// scratch; K2 = pure-write pixel expansion reading the L2-hot mask.
// Hypothesis: mixed R/W HBM stream capped all single-kernel variants at
// ~4.75 TB/s; unidirectional streams run faster each.

#define HH   132
#define WW   132
#define NBX  17
#define NBLK 289
#define KEEP 72
#define NPIX (HH*WW)
#define NTHREADS 256
#define CHUNK_ROWS 16
#define NCHUNK 9
#define ROW_F4 33

__device__ float g_mask[2048 * NBLK];   // block mask scratch (2.37 MB)

__device__ __forceinline__ void cp_async16(void* smem_ptr, const void* gptr) {
    uint32_t s = (uint32_t)__cvta_generic_to_shared(smem_ptr);
    asm volatile("cp.async.cg.shared.global [%0], [%1], 16;\n"
                 :: "r"(s), "l"(gptr));
}
#define CP_COMMIT() asm volatile("cp.async.commit_group;\n" ::: "memory")
#define CP_WAIT1()  asm volatile("cp.async.wait_group 1;\n" ::: "memory")
#define CP_WAIT0()  asm volatile("cp.async.wait_group 0;\n" ::: "memory")

// ---------------------------------------------------------------- K1: mask
__global__ __launch_bounds__(NTHREADS)
void mask_kernel(const float* __restrict__ in,
                 const int*  __restrict__ enabled)
{
    const int bc = blockIdx.x;
    const long long base = (long long)bc * NPIX;
    const int tid  = threadIdx.x;
    const int warp = tid >> 5;
    const int lane = tid & 31;

    if (*enabled == 0) return;          // K2 writes ones

    __shared__ float4 buf[2][CHUNK_ROWS * ROW_F4];
    __shared__ float  rbs[HH * NBX];
    __shared__ float  pooled[NBLK];
    __shared__ int    hist[32];
    __shared__ float  wmin[8], wmax[8];
    __shared__ float  s_minv, s_scale;
    __shared__ int    s_bb, s_chi, s_mcnt;
    __shared__ int    bblist[NBLK];

    if (tid < 32) hist[tid] = 0;
    if (tid == 0) s_mcnt = 0;

    const float4* src4 = (const float4*)(in + base);
    float* gm = g_mask + bc * NBLK;

    // ---- Phase A: double-buffered cp.async staging + smem reduction.
    {
        int n4 = CHUNK_ROWS * ROW_F4;
        for (int i = tid; i < n4; i += NTHREADS)
            cp_async16(&buf[0][i], src4 + i);
        CP_COMMIT();
    }
    for (int c = 0; c < NCHUNK; c++) {
        int r0 = c * CHUNK_ROWS;
        int nr = min(CHUNK_ROWS, HH - r0);
        if (c + 1 < NCHUNK) {
            int r0n = (c + 1) * CHUNK_ROWS;
            int nrn = min(CHUNK_ROWS, HH - r0n);
            int n4  = nrn * ROW_F4;
            const float4* g = src4 + r0n * ROW_F4;
            float4* b = buf[(c + 1) & 1];
            for (int i = tid; i < n4; i += NTHREADS)
                cp_async16(&b[i], g + i);
            CP_COMMIT();
            CP_WAIT1();
        } else {
            CP_WAIT0();
        }
        __syncthreads();

        const float* bf = (const float*)buf[c & 1];
        int tasks = nr * NBX;
        for (int t = tid; t < tasks; t += NTHREADS) {
            int rl = t / NBX;
            int bx = t - rl * NBX;
            const float* row = bf + rl * WW;
            float4 a = *(const float4*)(row + bx * 8);
            float4 b4;
            if (bx < 16) b4 = *(const float4*)(row + bx * 8 + 4);
            else         b4 = make_float4(0.f, 0.f, 0.f, 0.f);
            rbs[(r0 + rl) * NBX + bx] =
                  ((fabsf(a.x) + fabsf(b4.x)) + (fabsf(a.z) + fabsf(b4.z)))
                + ((fabsf(a.y) + fabsf(b4.y)) + (fabsf(a.w) + fabsf(b4.w)));
        }
        __syncthreads();
    }

    // ---- Phase B: block sums (linear over 8 rows, rows>=132 are pad) + min/max.
    float lmin = 3.4e38f, lmax = -3.4e38f;
    for (int b = tid; b < NBLK; b += NTHREADS) {
        int by = b / NBX;
        int bx = b - by * NBX;
        int y0 = by * 8;
        float s = 0.0f;
        #pragma unroll
        for (int r = 0; r < 8; r++) {
            int y = y0 + r;
            if (y < HH) s += rbs[y * NBX + bx];
        }
        pooled[b] = s;
        lmin = fminf(lmin, s);
        lmax = fmaxf(lmax, s);
    }
    #pragma unroll
    for (int off = 16; off > 0; off >>= 1) {
        lmin = fminf(lmin, __shfl_down_sync(0xffffffffu, lmin, off));
        lmax = fmaxf(lmax, __shfl_down_sync(0xffffffffu, lmax, off));
    }
    if (lane == 0) { wmin[warp] = lmin; wmax[warp] = lmax; }
    __syncthreads();

    if (warp == 0) {
        float mn = (lane < 8) ? wmin[lane] : 3.4e38f;
        float mx = (lane < 8) ? wmax[lane] : -3.4e38f;
        #pragma unroll
        for (int off = 4; off > 0; off >>= 1) {
            mn = fminf(mn, __shfl_down_sync(0xffffffffu, mn, off));
            mx = fmaxf(mx, __shfl_down_sync(0xffffffffu, mx, off));
        }
        if (lane == 0) {
            float r = mx - mn;
            s_minv  = mn;
            s_scale = (r > 0.0f) ? (32.0f / r) : 0.0f;
        }
    }
    __syncthreads();

    // ---- histogram
    {
        float minv = s_minv, scale = s_scale;
        for (int b = tid; b < NBLK; b += NTHREADS) {
            int bin = min((int)((pooled[b] - minv) * scale), 31);
            atomicAdd(&hist[bin], 1);
        }
    }
    __syncthreads();

    // ---- warp 0: suffix scan -> boundary bin bb, count strictly above (chi)
    if (warp == 0) {
        int cge = hist[lane];
        #pragma unroll
        for (int off = 1; off < 32; off <<= 1) {
            int t = __shfl_down_sync(0xffffffffu, cge, off);
            if (lane + off < 32) cge += t;
        }
        int cgt = __shfl_down_sync(0xffffffffu, cge, 1);
        if (lane == 31) cgt = 0;
        if (cgt < KEEP && cge >= KEEP) { s_bb = lane; s_chi = cgt; }
    }
    __syncthreads();

    // ---- classify; write decided blocks straight to scratch
    {
        float minv = s_minv, scale = s_scale;
        int bb = s_bb;
        for (int b = tid; b < NBLK; b += NTHREADS) {
            int bin = min((int)((pooled[b] - minv) * scale), 31);
            if (bin > bb)      gm[b] = 1.0f;
            else if (bin < bb) gm[b] = 0.0f;
            else               bblist[atomicAdd(&s_mcnt, 1)] = b;
        }
    }
    __syncthreads();

    // ---- exact rank inside boundary bin (tie: lower index wins)
    {
        int m = s_mcnt;
        int budget = KEEP - s_chi;
        for (int it = tid; it < m; it += NTHREADS) {
            int i = bblist[it];
            float vi = pooled[i];
            int c = 0;
            for (int j = 0; j < m; j++) {
                int jj = bblist[j];
                float vj = pooled[jj];
                c += (vj > vi) || (vj == vi && jj < i);
            }
            gm[i] = (c < budget) ? 1.0f : 0.0f;
        }
    }
}

// -------------------------------------------------------------- K2: expand
__global__ __launch_bounds__(NTHREADS)
void expand_kernel(const int* __restrict__ enabled,
                   float* __restrict__ out)
{
    const int bc = blockIdx.x;
    const long long base = (long long)bc * NPIX;
    const int tid  = threadIdx.x;
    const int warp = tid >> 5;
    const int lane = tid & 31;

    if (*enabled == 0) {
        float4 ones = make_float4(1.f, 1.f, 1.f, 1.f);
        float4* o4 = (float4*)(out + base);
        for (int p = tid; p < NPIX / 4; p += NTHREADS) o4[p] = ones;
        return;
    }

    __shared__ float hardm[NBLK];
    const float* gm = g_mask + bc * NBLK;
    for (int b = tid; b < NBLK; b += NTHREADS) hardm[b] = gm[b];
    __syncthreads();

    // expand to pixels, float4 stores (8 warps over 17 block-rows)
    for (int by = warp; by < NBX; by += 8) {
        float  mv  = hardm[by * NBX + (lane >> 1)];
        float  m16 = hardm[by * NBX + 16];
        float4 v4  = make_float4(mv, mv, mv, mv);
        float4 v16 = make_float4(m16, m16, m16, m16);
        int ylim = min(HH - by * 8, 8);
        float* obase = out + base + (by * 8) * WW;
        for (int r = 0; r < ylim; r++) {
            float* orow = obase + r * WW;
            *(float4*)(orow + lane * 4) = v4;
            if (lane == 0) *(float4*)(orow + 128) = v16;
        }
    }
}

extern "C" void kernel_launch(void* const* d_in, const int* in_sizes, int n_in,
                              void* d_out, int out_size)
{
    const float* features = (const float*)d_in[0];
    const int*   enabled  = (const int*)d_in[1];
    float* out = (float*)d_out;

    const int n_channels = out_size / NPIX;   // 2048
    mask_kernel<<<n_channels, NTHREADS>>>(features, enabled);
    expand_kernel<<<n_channels, NTHREADS>>>(enabled, out);
}

// round 9
// speedup vs baseline: 1.4190x; 1.4190x over previous
#include <cuda_runtime.h>
#include <cuda_bf16.h>
#include <cstdint>

// ChannelBlockImportanceGate: forward value == hard top-k block mask.
// features [8,256,132,132] f32, enabled int32. BLOCK=8 -> 17x17=289 blocks,
// keep = 72. Ties: lower flat index wins (lax.top_k).
//
// R9: R6 kernel (best known) with Phase D rebuilt as a linear coalesced
// copy: 17 row images staged in smem (reusing the cp.async buffer), then a
// grid-stride float4 stream write -- no straddled lines, no 1-lane tail
// stores. Read side + selection bitwise identical to R6.

#define HH   132
#define WW   132
#define NBX  17
#define NBLK 289
#define KEEP 72
#define NPIX (HH*WW)
#define NTHREADS 256
#define CHUNK_ROWS 16
#define NCHUNK 9
#define ROW_F4 33           // 132 floats = 33 float4 per row

__device__ __forceinline__ void cp_async16(void* smem_ptr, const void* gptr) {
    uint32_t s = (uint32_t)__cvta_generic_to_shared(smem_ptr);
    asm volatile("cp.async.cg.shared.global [%0], [%1], 16;\n"
                 :: "r"(s), "l"(gptr));
}
#define CP_COMMIT() asm volatile("cp.async.commit_group;\n" ::: "memory")
#define CP_WAIT1()  asm volatile("cp.async.wait_group 1;\n" ::: "memory")
#define CP_WAIT0()  asm volatile("cp.async.wait_group 0;\n" ::: "memory")

__global__ __launch_bounds__(NTHREADS)
void gate_kernel(const float* __restrict__ in,
                 const int*  __restrict__ enabled,
                 float* __restrict__ out)
{
    const int bc = blockIdx.x;
    const long long base = (long long)bc * NPIX;
    const int tid  = threadIdx.x;
    const int warp = tid >> 5;
    const int lane = tid & 31;

    if (*enabled == 0) {
        float4 ones = make_float4(1.f, 1.f, 1.f, 1.f);
        float4* o4 = (float4*)(out + base);
        for (int p = tid; p < NPIX / 4; p += NTHREADS) o4[p] = ones;
        return;
    }

    __shared__ float4 buf[2][CHUNK_ROWS * ROW_F4];   // staging; reused as rowpat
    __shared__ float  rbs[HH * NBX];
    __shared__ float  pooled[NBLK];
    __shared__ float  hardm[NBLK];
    __shared__ int    hist[32];
    __shared__ float  wmin[8], wmax[8];
    __shared__ float  s_minv, s_scale;
    __shared__ int    s_bb, s_chi, s_mcnt;
    __shared__ int    bblist[NBLK];

    if (tid < 32) hist[tid] = 0;
    if (tid == 0) s_mcnt = 0;

    const float4* src4 = (const float4*)(in + base);

    // ---- Phase A: double-buffered cp.async staging + smem reduction.
    {
        int n4 = CHUNK_ROWS * ROW_F4;
        for (int i = tid; i < n4; i += NTHREADS)
            cp_async16(&buf[0][i], src4 + i);
        CP_COMMIT();
    }
    for (int c = 0; c < NCHUNK; c++) {
        int r0 = c * CHUNK_ROWS;
        int nr = min(CHUNK_ROWS, HH - r0);
        if (c + 1 < NCHUNK) {
            int r0n = (c + 1) * CHUNK_ROWS;
            int nrn = min(CHUNK_ROWS, HH - r0n);
            int n4  = nrn * ROW_F4;
            const float4* g = src4 + r0n * ROW_F4;
            float4* b = buf[(c + 1) & 1];
            for (int i = tid; i < n4; i += NTHREADS)
                cp_async16(&b[i], g + i);
            CP_COMMIT();
            CP_WAIT1();
        } else {
            CP_WAIT0();
        }
        __syncthreads();

        const float* bf = (const float*)buf[c & 1];
        int tasks = nr * NBX;
        for (int t = tid; t < tasks; t += NTHREADS) {
            int rl = t / NBX;
            int bx = t - rl * NBX;
            const float* row = bf + rl * WW;
            float4 a = *(const float4*)(row + bx * 8);
            float4 b4;
            if (bx < 16) b4 = *(const float4*)(row + bx * 8 + 4);
            else         b4 = make_float4(0.f, 0.f, 0.f, 0.f);
            rbs[(r0 + rl) * NBX + bx] =
                  ((fabsf(a.x) + fabsf(b4.x)) + (fabsf(a.z) + fabsf(b4.z)))
                + ((fabsf(a.y) + fabsf(b4.y)) + (fabsf(a.w) + fabsf(b4.w)));
        }
        __syncthreads();
    }

    // ---- Phase B: block sums (linear over 8 rows, rows>=132 are pad) + min/max.
    float lmin = 3.4e38f, lmax = -3.4e38f;
    for (int b = tid; b < NBLK; b += NTHREADS) {
        int by = b / NBX;
        int bx = b - by * NBX;
        int y0 = by * 8;
        float s = 0.0f;
        #pragma unroll
        for (int r = 0; r < 8; r++) {
            int y = y0 + r;
            if (y < HH) s += rbs[y * NBX + bx];
        }
        pooled[b] = s;
        lmin = fminf(lmin, s);
        lmax = fmaxf(lmax, s);
    }
    #pragma unroll
    for (int off = 16; off > 0; off >>= 1) {
        lmin = fminf(lmin, __shfl_down_sync(0xffffffffu, lmin, off));
        lmax = fmaxf(lmax, __shfl_down_sync(0xffffffffu, lmax, off));
    }
    if (lane == 0) { wmin[warp] = lmin; wmax[warp] = lmax; }
    __syncthreads();

    // ---- warp 0: global min/max -> bin scale
    if (warp == 0) {
        float mn = (lane < 8) ? wmin[lane] : 3.4e38f;
        float mx = (lane < 8) ? wmax[lane] : -3.4e38f;
        #pragma unroll
        for (int off = 4; off > 0; off >>= 1) {
            mn = fminf(mn, __shfl_down_sync(0xffffffffu, mn, off));
            mx = fmaxf(mx, __shfl_down_sync(0xffffffffu, mx, off));
        }
        if (lane == 0) {
            float r = mx - mn;
            s_minv  = mn;
            s_scale = (r > 0.0f) ? (32.0f / r) : 0.0f;
        }
    }
    __syncthreads();

    // ---- histogram
    {
        float minv = s_minv, scale = s_scale;
        for (int b = tid; b < NBLK; b += NTHREADS) {
            int bin = min((int)((pooled[b] - minv) * scale), 31);
            atomicAdd(&hist[bin], 1);
        }
    }
    __syncthreads();

    // ---- warp 0: suffix scan -> boundary bin bb, count strictly above (chi)
    if (warp == 0) {
        int cge = hist[lane];
        #pragma unroll
        for (int off = 1; off < 32; off <<= 1) {
            int t = __shfl_down_sync(0xffffffffu, cge, off);
            if (lane + off < 32) cge += t;
        }
        int cgt = __shfl_down_sync(0xffffffffu, cge, 1);
        if (lane == 31) cgt = 0;
        if (cgt < KEEP && cge >= KEEP) { s_bb = lane; s_chi = cgt; }
    }
    __syncthreads();

    // ---- classify; collect boundary-bin items
    {
        float minv = s_minv, scale = s_scale;
        int bb = s_bb;
        for (int b = tid; b < NBLK; b += NTHREADS) {
            int bin = min((int)((pooled[b] - minv) * scale), 31);
            if (bin > bb)      hardm[b] = 1.0f;
            else if (bin < bb) hardm[b] = 0.0f;
            else               bblist[atomicAdd(&s_mcnt, 1)] = b;
        }
    }
    __syncthreads();

    // ---- exact rank inside boundary bin (tie: lower index wins)
    {
        int m = s_mcnt;
        int budget = KEEP - s_chi;
        for (int it = tid; it < m; it += NTHREADS) {
            int i = bblist[it];
            float vi = pooled[i];
            int c = 0;
            for (int j = 0; j < m; j++) {
                int jj = bblist[j];
                float vj = pooled[jj];
                c += (vj > vi) || (vj == vi && jj < i);
            }
            hardm[i] = (c < budget) ? 1.0f : 0.0f;
        }
    }
    __syncthreads();

    // ---- Phase D: build 17 row images in smem (reuse staging buffer),
    // then stream the channel out as a linear coalesced float4 copy.
    float4* rowpat = (float4*)buf;             // 17*33 = 561 float4 (8976 B)
    for (int i = tid; i < NBX * ROW_F4; i += NTHREADS) {
        int by = i / ROW_F4;                   // block-row
        int x4 = i - by * ROW_F4;              // float4 index within row
        float v = hardm[by * NBX + (x4 >> 1)]; // 4 pixels never straddle a block
        rowpat[i] = make_float4(v, v, v, v);
    }
    __syncthreads();

    {
        float4* o4 = (float4*)(out + base);
        for (int i = tid; i < NPIX / 4; i += NTHREADS) {
            int y  = i / ROW_F4;               // pixel row
            int x4 = i - y * ROW_F4;
            o4[i] = rowpat[(y >> 3) * ROW_F4 + x4];
        }
    }
}

extern "C" void kernel_launch(void* const* d_in, const int* in_sizes, int n_in,
                              void* d_out, int out_size)
{
    const float* features = (const float*)d_in[0];
    const int*   enabled  = (const int*)d_in[1];
    float* out = (float*)d_out;

    const int n_channels = out_size / NPIX;   // 2048
    gate_kernel<<<n_channels, NTHREADS>>>(features, enabled, out);
}

// round 10
// speedup vs baseline: 1.4233x; 1.0030x over previous
#include <cuda_runtime.h>
#include <cuda_bf16.h>
#include <cstdint>

// ChannelBlockImportanceGate: forward value == hard top-k block mask.
// features [8,256,132,132] f32, enabled int32. BLOCK=8 -> 17x17=289 blocks,
// keep = 72. Ties: lower flat index wins (lax.top_k).
//
// R10: R6 (best known) with a deeper read pipeline: triple-buffered cp.async
// + wait_group 2 -> two 8.4KB chunks in flight per CTA (~100KB/SM at 6
// CTAs/SM, +70% vs R6). All consumption, reduction trees, selection and
// store code byte-identical to R6.

#define HH   132
#define WW   132
#define NBX  17
#define NBLK 289
#define KEEP 72
#define NPIX (HH*WW)
#define NTHREADS 256
#define CHUNK_ROWS 16
#define NCHUNK 9
#define ROW_F4 33           // 132 floats = 33 float4 per row
#define NBUF 3

__device__ __forceinline__ void cp_async16(void* smem_ptr, const void* gptr) {
    uint32_t s = (uint32_t)__cvta_generic_to_shared(smem_ptr);
    asm volatile("cp.async.cg.shared.global [%0], [%1], 16;\n"
                 :: "r"(s), "l"(gptr));
}
#define CP_COMMIT() asm volatile("cp.async.commit_group;\n" ::: "memory")
#define CP_WAIT2()  asm volatile("cp.async.wait_group 2;\n" ::: "memory")
#define CP_WAIT0()  asm volatile("cp.async.wait_group 0;\n" ::: "memory")

__global__ __launch_bounds__(NTHREADS)
void gate_kernel(const float* __restrict__ in,
                 const int*  __restrict__ enabled,
                 float* __restrict__ out)
{
    const int bc = blockIdx.x;
    const long long base = (long long)bc * NPIX;
    const int tid  = threadIdx.x;
    const int warp = tid >> 5;
    const int lane = tid & 31;

    if (*enabled == 0) {
        float4 ones = make_float4(1.f, 1.f, 1.f, 1.f);
        float4* o4 = (float4*)(out + base);
        for (int p = tid; p < NPIX / 4; p += NTHREADS) o4[p] = ones;
        return;
    }

    __shared__ float4 buf[NBUF][CHUNK_ROWS * ROW_F4];   // 3 x 8448 B staging
    __shared__ float  rbs[HH * NBX];
    __shared__ float  pooled[NBLK];
    __shared__ float  hardm[NBLK];
    __shared__ int    hist[32];
    __shared__ float  wmin[8], wmax[8];
    __shared__ float  s_minv, s_scale;
    __shared__ int    s_bb, s_chi, s_mcnt;
    __shared__ int    bblist[NBLK];

    if (tid < 32) hist[tid] = 0;
    if (tid == 0) s_mcnt = 0;

    const float4* src4 = (const float4*)(in + base);

    // ---- Phase A: triple-buffered cp.async staging (2 chunks in flight).
    // prefill chunks 0 and 1 (one commit group each; both are full chunks)
    {
        int n4 = CHUNK_ROWS * ROW_F4;
        for (int i = tid; i < n4; i += NTHREADS)
            cp_async16(&buf[0][i], src4 + i);
        CP_COMMIT();
        const float4* g1 = src4 + CHUNK_ROWS * ROW_F4;
        for (int i = tid; i < n4; i += NTHREADS)
            cp_async16(&buf[1][i], g1 + i);
        CP_COMMIT();
    }
    for (int c = 0; c < NCHUNK; c++) {
        int r0 = c * CHUNK_ROWS;
        int nr = min(CHUNK_ROWS, HH - r0);

        // stage chunk c+2 (or an empty group to keep the wait count invariant)
        int cs = c + 2;
        if (cs < NCHUNK) {
            int r0s = cs * CHUNK_ROWS;
            int nrs = min(CHUNK_ROWS, HH - r0s);
            int n4  = nrs * ROW_F4;
            const float4* g = src4 + r0s * ROW_F4;
            float4* b = buf[cs % NBUF];
            for (int i = tid; i < n4; i += NTHREADS)
                cp_async16(&b[i], g + i);
        }
        CP_COMMIT();
        CP_WAIT2();                 // chunk c's group complete
        __syncthreads();

        const float* bf = (const float*)buf[c % NBUF];
        int tasks = nr * NBX;
        for (int t = tid; t < tasks; t += NTHREADS) {
            int rl = t / NBX;
            int bx = t - rl * NBX;
            const float* row = bf + rl * WW;
            float4 a = *(const float4*)(row + bx * 8);
            float4 b4;
            if (bx < 16) b4 = *(const float4*)(row + bx * 8 + 4);
            else         b4 = make_float4(0.f, 0.f, 0.f, 0.f);
            rbs[(r0 + rl) * NBX + bx] =
                  ((fabsf(a.x) + fabsf(b4.x)) + (fabsf(a.z) + fabsf(b4.z)))
                + ((fabsf(a.y) + fabsf(b4.y)) + (fabsf(a.w) + fabsf(b4.w)));
        }
        __syncthreads();
    }
    CP_WAIT0();

    // ---- Phase B: block sums (linear over 8 rows, rows>=132 are pad) + min/max.
    float lmin = 3.4e38f, lmax = -3.4e38f;
    for (int b = tid; b < NBLK; b += NTHREADS) {
        int by = b / NBX;
        int bx = b - by * NBX;
        int y0 = by * 8;
        float s = 0.0f;
        #pragma unroll
        for (int r = 0; r < 8; r++) {
            int y = y0 + r;
            if (y < HH) s += rbs[y * NBX + bx];
        }
        pooled[b] = s;
        lmin = fminf(lmin, s);
        lmax = fmaxf(lmax, s);
    }
    #pragma unroll
    for (int off = 16; off > 0; off >>= 1) {
        lmin = fminf(lmin, __shfl_down_sync(0xffffffffu, lmin, off));
        lmax = fmaxf(lmax, __shfl_down_sync(0xffffffffu, lmax, off));
    }
    if (lane == 0) { wmin[warp] = lmin; wmax[warp] = lmax; }
    __syncthreads();

    // ---- warp 0: global min/max -> bin scale
    if (warp == 0) {
        float mn = (lane < 8) ? wmin[lane] : 3.4e38f;
        float mx = (lane < 8) ? wmax[lane] : -3.4e38f;
        #pragma unroll
        for (int off = 4; off > 0; off >>= 1) {
            mn = fminf(mn, __shfl_down_sync(0xffffffffu, mn, off));
            mx = fmaxf(mx, __shfl_down_sync(0xffffffffu, mx, off));
        }
        if (lane == 0) {
            float r = mx - mn;
            s_minv  = mn;
            s_scale = (r > 0.0f) ? (32.0f / r) : 0.0f;
        }
    }
    __syncthreads();

    // ---- histogram
    {
        float minv = s_minv, scale = s_scale;
        for (int b = tid; b < NBLK; b += NTHREADS) {
            int bin = min((int)((pooled[b] - minv) * scale), 31);
            atomicAdd(&hist[bin], 1);
        }
    }
    __syncthreads();

    // ---- warp 0: suffix scan -> boundary bin bb, count strictly above (chi)
    if (warp == 0) {
        int cge = hist[lane];
        #pragma unroll
        for (int off = 1; off < 32; off <<= 1) {
            int t = __shfl_down_sync(0xffffffffu, cge, off);
            if (lane + off < 32) cge += t;
        }
        int cgt = __shfl_down_sync(0xffffffffu, cge, 1);
        if (lane == 31) cgt = 0;
        if (cgt < KEEP && cge >= KEEP) { s_bb = lane; s_chi = cgt; }
    }
    __syncthreads();

    // ---- classify; collect boundary-bin items
    {
        float minv = s_minv, scale = s_scale;
        int bb = s_bb;
        for (int b = tid; b < NBLK; b += NTHREADS) {
            int bin = min((int)((pooled[b] - minv) * scale), 31);
            if (bin > bb)      hardm[b] = 1.0f;
            else if (bin < bb) hardm[b] = 0.0f;
            else               bblist[atomicAdd(&s_mcnt, 1)] = b;
        }
    }
    __syncthreads();

    // ---- exact rank inside boundary bin (tie: lower index wins)
    {
        int m = s_mcnt;
        int budget = KEEP - s_chi;
        for (int it = tid; it < m; it += NTHREADS) {
            int i = bblist[it];
            float vi = pooled[i];
            int c = 0;
            for (int j = 0; j < m; j++) {
                int jj = bblist[j];
                float vj = pooled[jj];
                c += (vj > vi) || (vj == vi && jj < i);
            }
            hardm[i] = (c < budget) ? 1.0f : 0.0f;
        }
    }
    __syncthreads();

    // ---- Phase D: expand to pixels, float4 stores
    for (int by = warp; by < NBX; by += 8) {
        float  mv  = hardm[by * NBX + (lane >> 1)];
        float  m16 = hardm[by * NBX + 16];
        float4 v4  = make_float4(mv, mv, mv, mv);
        float4 v16 = make_float4(m16, m16, m16, m16);
        int ylim = min(HH - by * 8, 8);
        float* obase = out + base + (by * 8) * WW;
        for (int r = 0; r < ylim; r++) {
            float* orow = obase + r * WW;
            *(float4*)(orow + lane * 4) = v4;
            if (lane == 0) *(float4*)(orow + 128) = v16;
        }
    }
}

extern "C" void kernel_launch(void* const* d_in, const int* in_sizes, int n_in,
                              void* d_out, int out_size)
{
    const float* features = (const float*)d_in[0];
    const int*   enabled  = (const int*)d_in[1];
    float* out = (float*)d_out;

    const int n_channels = out_size / NPIX;   // 2048
    gate_kernel<<<n_channels, NTHREADS>>>(features, enabled, out);
}